// round 1
// baseline (speedup 1.0000x reference)
#include <cuda_runtime.h>

// CodedNet: z[b,i,j] = sum_ch x[b,i,j,ch] * bk[(i-ch)%256, j, ch]
// x  : [32, 256, 256, 28] f32  (channel contiguous)
// bk : [256, 256, 28]     f32
// out: [32, 256, 256]     f32
//
// Design: block = (one i-row, one 128-wide j-tile, ALL 32 batches).
//  - mask gathered once per thread into 7 float4 registers (batch-invariant)
//  - x staged coalesced through double-buffered SMEM (14336 B per buffer)
//  - compute: 7x LDS.128 (conflict-free at 112B stride) + dot4 + coalesced STG

#define PDIM 256
#define CHN  28
#define JT   128                       // j per block
#define NB   32                        // batches per block
#define TILE_FLOATS (JT * CHN)         // 3584
#define TILE_VEC    (TILE_FLOATS / 4)  // 896

__global__ __launch_bounds__(128)
void codednet_kernel(const float* __restrict__ x,
                     const float* __restrict__ bk,
                     float* __restrict__ out)
{
    __shared__ float4 sbuf[2][TILE_VEC];

    const int tid = threadIdx.x;          // 0..127 -> j within tile
    const int bx  = blockIdx.x;           // 0..511
    const int i   = bx >> 1;              // 0..255
    const int j0  = (bx & 1) * JT;        // 0 or 128
    const int j   = j0 + tid;

    // ---- gather per-pixel mask column into registers (batch-invariant) ----
    float m[CHN];
#pragma unroll
    for (int ch = 0; ch < CHN; ch++) {
        int r = (i - ch + PDIM) & (PDIM - 1);
        m[ch] = __ldg(&bk[((size_t)r * PDIM + j) * CHN + ch]);
    }
    float4 mv[7];
#pragma unroll
    for (int k = 0; k < 7; k++)
        mv[k] = make_float4(m[4*k], m[4*k+1], m[4*k+2], m[4*k+3]);

    // ---- batch loop with double-buffered coalesced staging ----
    const float4* xv = reinterpret_cast<const float4*>(x);
    const size_t tile_off = ((size_t)i * PDIM + j0) * CHN / 4;  // float4 offset within a batch
    const size_t bstride  = (size_t)PDIM * PDIM * CHN / 4;      // float4 per batch

    float4 r[7];
#pragma unroll
    for (int k = 0; k < 7; k++)
        r[k] = xv[tile_off + tid + JT * k];

    for (int b = 0; b < NB; b++) {
        float4* buf = sbuf[b & 1];
#pragma unroll
        for (int k = 0; k < 7; k++)
            buf[tid + JT * k] = r[k];

        __syncthreads();

        if (b + 1 < NB) {
            const size_t off = tile_off + (size_t)(b + 1) * bstride;
#pragma unroll
            for (int k = 0; k < 7; k++)
                r[k] = xv[off + tid + JT * k];
        }

        // thread tid owns pixel j: floats [tid*28 .. tid*28+27] = float4 idx tid*7+k
        const float4* cb = sbuf[b & 1];
        float acc = 0.0f;
#pragma unroll
        for (int k = 0; k < 7; k++) {
            float4 v = cb[tid * 7 + k];
            acc += v.x * mv[k].x + v.y * mv[k].y + v.z * mv[k].z + v.w * mv[k].w;
        }
        out[((size_t)b * PDIM + i) * PDIM + j] = acc;
        // buffer-reuse safety: STS into this buffer again only at iter b+2,
        // which is ordered after the iter b+1 __syncthreads that all threads
        // reach only after finishing this compute.
    }
}

extern "C" void kernel_launch(void* const* d_in, const int* in_sizes, int n_in,
                              void* d_out, int out_size)
{
    const float* x  = (const float*)d_in[0];
    const float* bk = (const float*)d_in[1];
    float* out = (float*)d_out;
    (void)in_sizes; (void)n_in; (void)out_size;

    codednet_kernel<<<PDIM * (PDIM / JT), 128>>>(x, bk, out);
}